// round 15
// baseline (speedup 1.0000x reference)
#include <cuda_runtime.h>
#include <cstdint>
#include <cuda_bf16.h>
#include <mma.h>
#include <math.h>

using namespace nvcuda;

// Problem constants
#define Bc 2
#define Nc 32768
#define Kc 16
#define Dc 256
#define Ac 64
#define Vc 64
#define Hc 512
#define Mrows (Bc * Nc)   // 65536
#define NK (Nc * Kc)      // 524288

typedef __nv_bfloat16 bf16;

// -------- scratch (device globals) --------
__device__ bf16  g_lnb [(size_t)Mrows * Dc];
__device__ bf16  g_q   [(size_t)Mrows * Ac];
__device__ bf16  g_k   [(size_t)Mrows * Ac];
__device__ bf16  g_v   [(size_t)Mrows * Vc];
__device__ bf16  g_ctxb[(size_t)Mrows * Vc];
__device__ float g_x1  [(size_t)Mrows * Dc];
__device__ bf16  g_h2b [(size_t)Mrows * Dc];
__device__ bf16  g_hidb[(size_t)Mrows * Hc];
__device__ bf16  g_ra  [(size_t)NK * Ac];      // ra + bpa2 (bf16)
__device__ bf16  g_rv  [(size_t)NK * Vc];      // rv + bpv2 (bf16)

// bf16 weight copies
__device__ bf16 g_Wqb  [Dc * Ac];
__device__ bf16 g_Wkb  [Dc * Ac];
__device__ bf16 g_Wvb  [Dc * Vc];
__device__ bf16 g_Wob  [Vc * Dc];
__device__ bf16 g_Wf1b [Dc * Hc];
__device__ bf16 g_Wf2b [Hc * Dc];
__device__ bf16 g_Wpa2b[Ac * Ac];
__device__ bf16 g_Wpv2b[Vc * Vc];
__device__ bf16 g_Ws1b [Ac * Ac];

__device__ __forceinline__ float fast_tanh(float x) {
    float y;
    asm("tanh.approx.f32 %0, %1;" : "=f"(y) : "f"(x));
    return y;
}

__device__ __forceinline__ void cp16(void* dst, const void* src) {
    unsigned int s = (unsigned int)__cvta_generic_to_shared(dst);
    asm volatile("cp.async.cg.shared.global [%0], [%1], 16;" :: "r"(s), "l"(src));
}
__device__ __forceinline__ void cp_commit() {
    asm volatile("cp.async.commit_group;" ::: "memory");
}
__device__ __forceinline__ void cp_wait0() {
    asm volatile("cp.async.wait_group 0;" ::: "memory");
}

// ============================================================
// Weight fp32 -> bf16 conversion (incl. attention small weights)
// ============================================================
__global__ void k_cvtw(const float* __restrict__ Wq, const float* __restrict__ Wk,
                       const float* __restrict__ Wv, const float* __restrict__ Wo,
                       const float* __restrict__ Wf1, const float* __restrict__ Wf2,
                       const float* __restrict__ Wpa2, const float* __restrict__ Wpv2,
                       const float* __restrict__ Ws1) {
    int i = blockIdx.x * blockDim.x + threadIdx.x;
    const int S1 = Dc * Ac;
    const int S2 = S1 * 2;
    const int S3 = S1 * 3;
    const int S4 = S3 + Vc * Dc;
    const int S5 = S4 + Dc * Hc;
    const int S6 = S5 + Hc * Dc;
    const int S7 = S6 + Ac * Ac;
    const int S8 = S7 + Vc * Vc;
    const int S9 = S8 + Ac * Ac;
    if (i >= S9) return;
    if (i < S1)       g_Wqb  [i]      = __float2bfloat16(Wq  [i]);
    else if (i < S2)  g_Wkb  [i - S1] = __float2bfloat16(Wk  [i - S1]);
    else if (i < S3)  g_Wvb  [i - S2] = __float2bfloat16(Wv  [i - S2]);
    else if (i < S4)  g_Wob  [i - S3] = __float2bfloat16(Wo  [i - S3]);
    else if (i < S5)  g_Wf1b [i - S4] = __float2bfloat16(Wf1 [i - S4]);
    else if (i < S6)  g_Wf2b [i - S5] = __float2bfloat16(Wf2 [i - S5]);
    else if (i < S7)  g_Wpa2b[i - S6] = __float2bfloat16(Wpa2[i - S6]);
    else if (i < S8)  g_Wpv2b[i - S7] = __float2bfloat16(Wpv2[i - S7]);
    else              g_Ws1b [i - S8] = __float2bfloat16(Ws1 [i - S8]);
}

// ============================================================
// LayerNorm: out(bf16) = LN(in)*g + b.  one warp per row.
// ============================================================
__global__ void k_ln(const float* __restrict__ in,
                     const float* __restrict__ g, const float* __restrict__ b,
                     bf16* __restrict__ out) {
    const int row = blockIdx.x * 8 + (threadIdx.x >> 5);
    const int lane = threadIdx.x & 31;
    const float* p = in + (size_t)row * Dc;
    float v[8];
    #pragma unroll
    for (int i = 0; i < 8; i++) v[i] = p[lane + 32 * i];
    float s = 0.f;
    #pragma unroll
    for (int i = 0; i < 8; i++) s += v[i];
    #pragma unroll
    for (int o = 16; o; o >>= 1) s += __shfl_xor_sync(~0u, s, o);
    float m = s * (1.0f / Dc);
    float var = 0.f;
    #pragma unroll
    for (int i = 0; i < 8; i++) { float d = v[i] - m; var += d * d; }
    #pragma unroll
    for (int o = 16; o; o >>= 1) var += __shfl_xor_sync(~0u, var, o);
    float rstd = rsqrtf(var * (1.0f / Dc) + 1e-5f);
    bf16* q = out + (size_t)row * Dc;
    #pragma unroll
    for (int i = 0; i < 8; i++) {
        int d = lane + 32 * i;
        q[d] = __float2bfloat16((v[i] - m) * rstd * g[d] + b[d]);
    }
}

// ============================================================
// Pipelined bf16 wmma GEMM core.  BM=128, BK_/BN_ templated.
// ============================================================
#define BM 128

template<int BN_, int BK_, int ACT, bool HAS_RES, bool OUT_BF16>
__device__ __forceinline__ void gemm_core_bf16(
        const bf16* __restrict__ A, const bf16* __restrict__ B,
        const float* __restrict__ bias, const float* __restrict__ Res,
        void* __restrict__ Cv, int N, int K, int row0, int col0) {
    constexpr int LDA_ = BK_ + 8;
    constexpr int LDB_ = BN_ + 8;
    constexpr int ASZ  = BM * LDA_;
    constexpr int BSZ  = BK_ * LDB_;
    constexpr int NFRAG = BN_ / 32;
    constexpr int WCOLS = 16 * NFRAG;
    constexpr int LDE_  = WCOLS + 4;
    constexpr int AT = (BM * BK_ / 8) / 256;
    constexpr int BT = (BK_ * BN_ / 8 + 255) / 256;
    constexpr int KCH = BK_ / 8;

    extern __shared__ char smraw[];
    bf16* sb = (bf16*)smraw;
    bf16* Abuf[2] = { sb, sb + ASZ + BSZ };
    bf16* Bbuf[2] = { sb + ASZ, sb + 2 * ASZ + BSZ };

    const int tid = threadIdx.x;
    const int warp = tid >> 5, lane = tid & 31;
    const int wm = warp & 3;
    const int wn = warp >> 2;

    wmma::fragment<wmma::accumulator, 16, 16, 16, float> cf[2][NFRAG];
    #pragma unroll
    for (int i = 0; i < 2; i++)
        #pragma unroll
        for (int j = 0; j < NFRAG; j++) wmma::fill_fragment(cf[i][j], 0.f);

    {
        #pragma unroll
        for (int i = 0; i < AT; i++) {
            int idx = tid + i * 256;
            int r = idx / KCH, c8 = (idx % KCH) * 8;
            cp16(&Abuf[0][r * LDA_ + c8], A + (size_t)(row0 + r) * K + c8);
        }
        #pragma unroll
        for (int i = 0; i < BT; i++) {
            int idx = tid + i * 256;
            if (BT * 256 == BK_ * BN_ / 8 || idx < BK_ * BN_ / 8) {
                int r = idx / (BN_ / 8), c8 = (idx % (BN_ / 8)) * 8;
                cp16(&Bbuf[0][r * LDB_ + c8], B + (size_t)r * N + col0 + c8);
            }
        }
        cp_commit();
    }

    int buf = 0;
    for (int k0 = 0; k0 < K; k0 += BK_) {
        cp_wait0();
        __syncthreads();
        if (k0 + BK_ < K) {
            bf16* As = Abuf[buf ^ 1];
            bf16* Bs = Bbuf[buf ^ 1];
            #pragma unroll
            for (int i = 0; i < AT; i++) {
                int idx = tid + i * 256;
                int r = idx / KCH, c8 = (idx % KCH) * 8;
                cp16(&As[r * LDA_ + c8], A + (size_t)(row0 + r) * K + (k0 + BK_) + c8);
            }
            #pragma unroll
            for (int i = 0; i < BT; i++) {
                int idx = tid + i * 256;
                if (BT * 256 == BK_ * BN_ / 8 || idx < BK_ * BN_ / 8) {
                    int r = idx / (BN_ / 8), c8 = (idx % (BN_ / 8)) * 8;
                    cp16(&Bs[r * LDB_ + c8], B + (size_t)(k0 + BK_ + r) * N + col0 + c8);
                }
            }
            cp_commit();
        }
        const bf16* As = Abuf[buf];
        const bf16* Bs = Bbuf[buf];
        #pragma unroll
        for (int kk = 0; kk < BK_; kk += 16) {
            wmma::fragment<wmma::matrix_a, 16, 16, 16, bf16, wmma::row_major> af[2];
            wmma::fragment<wmma::matrix_b, 16, 16, 16, bf16, wmma::row_major> bf[NFRAG];
            #pragma unroll
            for (int i = 0; i < 2; i++)
                wmma::load_matrix_sync(af[i], &As[(wm * 32 + i * 16) * LDA_ + kk], LDA_);
            #pragma unroll
            for (int j = 0; j < NFRAG; j++)
                wmma::load_matrix_sync(bf[j], &Bs[kk * LDB_ + wn * WCOLS + j * 16], LDB_);
            #pragma unroll
            for (int i = 0; i < 2; i++)
                #pragma unroll
                for (int j = 0; j < NFRAG; j++)
                    wmma::mma_sync(cf[i][j], af[i], bf[j], cf[i][j]);
        }
        buf ^= 1;
    }

    __syncthreads();
    float* fs = (float*)smraw;
    float* Ep = fs + warp * (16 * LDE_);

    const int gr00 = row0 + wm * 32;
    const int gcb  = col0 + wn * WCOLS;
    float bvv[WCOLS / 32];
    #pragma unroll
    for (int cc = 0; cc < WCOLS / 32; cc++) bvv[cc] = bias[gcb + cc * 32 + lane];

    #pragma unroll
    for (int i = 0; i < 2; i++) {
        #pragma unroll
        for (int j = 0; j < NFRAG; j++)
            wmma::store_matrix_sync(&Ep[j * 16], cf[i][j], LDE_, wmma::mem_row_major);
        __syncwarp();
        const int gr0 = gr00 + i * 16;
        #pragma unroll
        for (int cc = 0; cc < WCOLS / 32; cc++) {
            const int cI = lane + cc * 32;
            #pragma unroll 4
            for (int r = 0; r < 16; r++) {
                float z = Ep[r * LDE_ + cI] + bvv[cc];
                if (ACT == 1) z = 0.5f * z * (1.f + erff(z * 0.70710678118654752f));
                if (HAS_RES) z += Res[(size_t)(gr0 + r) * N + gcb + cI];
                size_t off = (size_t)(gr0 + r) * N + gcb + cI;
                if (OUT_BF16) ((bf16*)Cv)[off] = __float2bfloat16(z);
                else          ((float*)Cv)[off] = z;
            }
        }
        __syncwarp();
    }
}

__global__ void __launch_bounds__(256, 2) k_qkv2(const float* __restrict__ bq,
                                                 const float* __restrict__ bk,
                                                 const float* __restrict__ bv) {
    const bf16* B; const float* bias; bf16* C;
    if (blockIdx.y == 0)      { B = g_Wqb; bias = bq; C = g_q; }
    else if (blockIdx.y == 1) { B = g_Wkb; bias = bk; C = g_k; }
    else                      { B = g_Wvb; bias = bv; C = g_v; }
    gemm_core_bf16<64, 32, 0, false, true>(g_lnb, B, bias, nullptr, C, 64, Dc, blockIdx.x * BM, 0);
}

__global__ void __launch_bounds__(256, 2) k_wo(const float* __restrict__ x,
                                               const float* __restrict__ bo) {
    gemm_core_bf16<128, 64, 0, true, false>(g_ctxb, g_Wob, bo, x, g_x1, Dc, Vc,
                                            blockIdx.x * BM, blockIdx.y * 128);
}

__global__ void __launch_bounds__(256, 2) k_ffn1(const float* __restrict__ bf1) {
    gemm_core_bf16<128, 64, 1, false, true>(g_h2b, g_Wf1b, bf1, nullptr, g_hidb, Hc, Dc,
                                            blockIdx.x * BM, blockIdx.y * 128);
}

__global__ void __launch_bounds__(256, 2) k_ffn2(const float* __restrict__ bf2,
                                                 float* __restrict__ C) {
    gemm_core_bf16<128, 64, 0, true, false>(g_hidb, g_Wf2b, bf2, g_x1, C, Dc, Hc,
                                            blockIdx.x * BM, blockIdx.y * 128);
}

// ============================================================
// k_rarv: one pass (a or v) per blockIdx.y; 512-row tile.
// ============================================================
#define LDH 72   // bf16 stride
#define LDE2 68  // fp32 bias tile stride
#define LDE3 36  // fp32 half-pair staging stride
#define RT 512

__global__ void __launch_bounds__(256, 2) k_rarv(
        const float* __restrict__ rel,
        const float* __restrict__ Wpa1, const float* __restrict__ bpa1,
        const float* __restrict__ bpa2,
        const float* __restrict__ Wpv1, const float* __restrict__ bpv1,
        const float* __restrict__ bpv2) {
    extern __shared__ float sm[];
    float* rel_s = sm;                    // 1536
    float* biasT = rel_s + 1536;          // 1088
    float* w1s   = biasT + 1088;          // 256
    float* stg   = w1s + 256;             // 4608
    bf16*  W2s   = (bf16*)(stg + 4608);   // 64*72
    bf16*  Hb    = W2s + 64 * LDH;        // 128*72

    const int tid = threadIdx.x, lane = tid & 31, warp = tid >> 5;
    const int g0 = blockIdx.x * RT;
    const int pp = blockIdx.y;

    const float* W1g = pp ? Wpv1 : Wpa1;
    const float* B1g = pp ? bpv1 : bpa1;
    const float* B2g = pp ? bpv2 : bpa2;
    const bf16*  W2g = pp ? g_Wpv2b : g_Wpa2b;
    bf16* out = pp ? g_rv : g_ra;

    for (int i = tid; i < RT * 3; i += 256) rel_s[i] = rel[(size_t)g0 * 3 + i];
    for (int i = tid; i < 4096; i += 256) {
        int r = i >> 6, c = i & 63;
        W2s[r * LDH + c] = W2g[i];
    }
    for (int i = tid; i < 192; i += 256) w1s[i] = W1g[i];
    if (tid < 64) w1s[192 + tid] = B1g[tid];
    for (int i = tid; i < 16 * LDE2; i += 256) {
        int c = i % LDE2;
        biasT[i] = (c < 64) ? B2g[c] : 0.f;
    }
    __syncthreads();

    wmma::fragment<wmma::matrix_b, 16, 16, 16, bf16, wmma::row_major> bfr[4][4];
    #pragma unroll
    for (int k4 = 0; k4 < 4; k4++)
        #pragma unroll
        for (int j = 0; j < 4; j++)
            wmma::load_matrix_sync(bfr[k4][j], &W2s[(k4 * 16) * LDH + j * 16], LDH);

    const int j0 = 2 * lane, j1 = 2 * lane + 1;
    const float* W1 = w1s;
    for (int chunk = 0; chunk < 4; chunk++) {
        const int r0 = chunk * 128;
        #pragma unroll 4
        for (int pass = 0; pass < 16; pass++) {
            int r = pass * 8 + warp;
            float x0 = rel_s[(r0 + r) * 3];
            float x1 = rel_s[(r0 + r) * 3 + 1];
            float x2 = rel_s[(r0 + r) * 3 + 2];
            float h0 = fmaxf(fmaf(x2, W1[128 + j0], fmaf(x1, W1[64 + j0], fmaf(x0, W1[j0], W1[192 + j0]))), 0.f);
            float h1 = fmaxf(fmaf(x2, W1[128 + j1], fmaf(x1, W1[64 + j1], fmaf(x0, W1[j1], W1[192 + j1]))), 0.f);
            *(__nv_bfloat162*)&Hb[r * LDH + j0] = __floats2bfloat162_rn(h0, h1);
        }
        __syncthreads();

        wmma::fragment<wmma::accumulator, 16, 16, 16, float> acc[4];
        #pragma unroll
        for (int j = 0; j < 4; j++)
            wmma::load_matrix_sync(acc[j], &biasT[j * 16], LDE2, wmma::mem_row_major);
        #pragma unroll
        for (int k4 = 0; k4 < 4; k4++) {
            wmma::fragment<wmma::matrix_a, 16, 16, 16, bf16, wmma::row_major> af;
            wmma::load_matrix_sync(af, &Hb[(warp * 16) * LDH + k4 * 16], LDH);
            #pragma unroll
            for (int j = 0; j < 4; j++)
                wmma::mma_sync(acc[j], af, bfr[k4][j], acc[j]);
        }
        float* wstg = stg + warp * (16 * LDE3);
        const int row = lane & 15, half = lane >> 4;
        #pragma unroll
        for (int jp = 0; jp < 2; jp++) {
            wmma::store_matrix_sync(&wstg[0],  acc[jp * 2],     LDE3, wmma::mem_row_major);
            wmma::store_matrix_sync(&wstg[16], acc[jp * 2 + 1], LDE3, wmma::mem_row_major);
            __syncwarp();
            const float* rp = &wstg[row * LDE3 + half * 16];
            const size_t G = (size_t)(g0 + r0 + warp * 16 + row) * 64 + jp * 32 + half * 16;
            #pragma unroll
            for (int c = 0; c < 2; c++) {
                float4 a = *(const float4*)(rp + c * 8);
                float4 b = *(const float4*)(rp + c * 8 + 4);
                bf16 tmp[8];
                tmp[0] = __float2bfloat16(a.x); tmp[1] = __float2bfloat16(a.y);
                tmp[2] = __float2bfloat16(a.z); tmp[3] = __float2bfloat16(a.w);
                tmp[4] = __float2bfloat16(b.x); tmp[5] = __float2bfloat16(b.y);
                tmp[6] = __float2bfloat16(b.z); tmp[7] = __float2bfloat16(b.w);
                *(uint4*)&out[G + c * 8] = *(uint4*)tmp;
            }
            __syncwarp();
        }
        __syncthreads();
    }
}

// ============================================================
// k_score: 512-row tile x batch; bf16 q/k gathers; fused softmax+ctx.
// ============================================================
__global__ void __launch_bounds__(256, 3) k_score(
        const int* __restrict__ knn_idx,
        const float* __restrict__ bs1,
        const float* __restrict__ Ws2, const float* __restrict__ bs2) {
    extern __shared__ float sm[];
    bf16*  q_sb  = (bf16*)sm;             // 2048 bf16 = 1024 floats
    float* biasT = sm + 1024;             // 1088
    float* wS2s  = biasT + 1088;          // 64
    float* sc_s  = wS2s + 64;             // 512
    float* stg   = sc_s + 512;            // 4608
    int*   idx_s = (int*)(stg + 4608);    // 512
    bf16*  Ws1b  = (bf16*)(idx_s + 512);  // 64*72
    bf16*  tb    = Ws1b + 64 * LDH;       // 128*72

    const int tid = threadIdx.x, lane = tid & 31, warp = tid >> 5;
    const int g0 = blockIdx.x * RT;
    const int b  = blockIdx.y;
    const int row = lane & 15, half = lane >> 4;

    for (int i = tid; i < 4096; i += 256) {
        int r = i >> 6, c = i & 63;
        Ws1b[r * LDH + c] = g_Ws1b[i];
    }
    for (int i = tid; i < 2048; i += 256) {
        int pt = i >> 6, a = i & 63;
        q_sb[i] = g_q[((size_t)b * Nc + (g0 >> 4) + pt) * 64 + a];
    }
    for (int i = tid; i < 512; i += 256) idx_s[i] = knn_idx[g0 + i];
    for (int i = tid; i < 16 * LDE2; i += 256) {
        int c = i % LDE2;
        biasT[i] = (c < 64) ? bs1[c] : 0.f;
    }
    if (tid < 64) wS2s[tid] = Ws2[tid];
    const float bS2v = bs2[0];
    __syncthreads();

    const int j0 = 2 * lane;
    for (int chunk = 0; chunk < 4; chunk++) {
        const int r0 = chunk * 128;
        #pragma unroll 4
        for (int pass = 0; pass < 16; pass++) {
            int r = pass * 8 + warp;
            int lr = r0 + r;
            int nb = idx_s[lr];
            __nv_bfloat162 qv = *(const __nv_bfloat162*)&q_sb[(lr >> 4) * 64 + j0];
            __nv_bfloat162 kv = *(const __nv_bfloat162*)&g_k[((size_t)b * Nc + nb) * 64 + j0];
            __nv_bfloat162 rab = *(const __nv_bfloat162*)&g_ra[(size_t)(g0 + lr) * 64 + j0];
            float t0 = fast_tanh(__bfloat162float(qv.x) - __bfloat162float(kv.x) + __bfloat162float(rab.x));
            float t1 = fast_tanh(__bfloat162float(qv.y) - __bfloat162float(kv.y) + __bfloat162float(rab.y));
            *(__nv_bfloat162*)&tb[r * LDH + j0] = __floats2bfloat162_rn(t0, t1);
        }
        __syncthreads();

        wmma::fragment<wmma::accumulator, 16, 16, 16, float> acc[4];
        #pragma unroll
        for (int j = 0; j < 4; j++)
            wmma::load_matrix_sync(acc[j], &biasT[j * 16], LDE2, wmma::mem_row_major);
        #pragma unroll
        for (int k4 = 0; k4 < 4; k4++) {
            wmma::fragment<wmma::matrix_a, 16, 16, 16, bf16, wmma::row_major> af;
            wmma::load_matrix_sync(af, &tb[(warp * 16) * LDH + k4 * 16], LDH);
            #pragma unroll
            for (int j = 0; j < 4; j++) {
                wmma::fragment<wmma::matrix_b, 16, 16, 16, bf16, wmma::row_major> bw;
                wmma::load_matrix_sync(bw, &Ws1b[(k4 * 16) * LDH + j * 16], LDH);
                wmma::mma_sync(acc[j], af, bw, acc[j]);
            }
        }
        float* wstg = stg + warp * (16 * LDE3);
        float p = 0.f;
        #pragma unroll
        for (int jp = 0; jp < 2; jp++) {
            wmma::store_matrix_sync(&wstg[0],  acc[jp * 2],     LDE3, wmma::mem_row_major);
            wmma::store_matrix_sync(&wstg[16], acc[jp * 2 + 1], LDE3, wmma::mem_row_major);
            __syncwarp();
            const float* rp = &wstg[row * LDE3 + half * 16];
            const int cb = jp * 32 + half * 16;
            #pragma unroll
            for (int c = 0; c < 4; c++) {
                float4 u = *(const float4*)(rp + c * 4);
                p = fmaf(fmaxf(u.x, 0.f), wS2s[cb + c * 4 + 0], p);
                p = fmaf(fmaxf(u.y, 0.f), wS2s[cb + c * 4 + 1], p);
                p = fmaf(fmaxf(u.z, 0.f), wS2s[cb + c * 4 + 2], p);
                p = fmaf(fmaxf(u.w, 0.f), wS2s[cb + c * 4 + 3], p);
            }
            __syncwarp();
        }
        p += __shfl_xor_sync(~0u, p, 16);
        if (half == 0)
            sc_s[r0 + warp * 16 + row] = p + bS2v;
        __syncthreads();
    }

    // ---- fused softmax + context: warp handles 4 points ----
    #pragma unroll
    for (int pi = 0; pi < 4; pi++) {
        const int pl = warp * 4 + pi;
        const int n  = (g0 >> 4) + pl;
        float s = -INFINITY;
        int nbl = 0;
        if (lane < 16) {
            s = sc_s[pl * 16 + lane] * 0.125f;
            nbl = idx_s[pl * 16 + lane];
        }
        float mx = s;
        #pragma unroll
        for (int o = 16; o; o >>= 1) mx = fmaxf(mx, __shfl_xor_sync(~0u, mx, o));
        float e = (lane < 16) ? __expf(s - mx) : 0.f;
        float se = e;
        #pragma unroll
        for (int o = 16; o; o >>= 1) se += __shfl_xor_sync(~0u, se, o);
        float wt = e / se;

        float acc0 = 0.f, acc1 = 0.f;
        #pragma unroll
        for (int kk = 0; kk < 16; kk++) {
            float ww = __shfl_sync(~0u, wt, kk);
            int nb  = __shfl_sync(~0u, nbl, kk);
            const bf16* vp = g_v + ((size_t)b * Nc + nb) * 64;
            const bf16* rvp = g_rv + (size_t)(g0 + pl * 16 + kk) * 64;
            acc0 += ww * (__bfloat162float(vp[lane])      + __bfloat162float(rvp[lane]));
            acc1 += ww * (__bfloat162float(vp[lane + 32]) + __bfloat162float(rvp[lane + 32]));
        }
        size_t obase = ((size_t)b * Nc + n) * 64;
        g_ctxb[obase + lane]      = __float2bfloat16(acc0);
        g_ctxb[obase + lane + 32] = __float2bfloat16(acc1);
    }
}

// ============================================================
extern "C" void kernel_launch(void* const* d_in, const int* in_sizes, int n_in,
                              void* d_out, int out_size) {
    const float* x       = (const float*)d_in[0];
    const int*   knn_idx = (const int*)  d_in[1];
    const float* rel     = (const float*)d_in[2];
    const float* g1 = (const float*)d_in[3];
    const float* b1 = (const float*)d_in[4];
    const float* g2 = (const float*)d_in[5];
    const float* b2 = (const float*)d_in[6];
    const float* Wq = (const float*)d_in[7];
    const float* bq = (const float*)d_in[8];
    const float* Wk = (const float*)d_in[9];
    const float* bk = (const float*)d_in[10];
    const float* Wv = (const float*)d_in[11];
    const float* bv = (const float*)d_in[12];
    const float* Wo = (const float*)d_in[13];
    const float* bo = (const float*)d_in[14];
    const float* Wpa1 = (const float*)d_in[15];
    const float* bpa1 = (const float*)d_in[16];
    const float* Wpa2 = (const float*)d_in[17];
    const float* bpa2 = (const float*)d_in[18];
    const float* Wpv1 = (const float*)d_in[19];
    const float* bpv1 = (const float*)d_in[20];
    const float* Wpv2 = (const float*)d_in[21];
    const float* bpv2 = (const float*)d_in[22];
    const float* Ws1  = (const float*)d_in[23];
    const float* bs1  = (const float*)d_in[24];
    const float* Ws2  = (const float*)d_in[25];
    const float* bs2  = (const float*)d_in[26];
    const float* Wf1  = (const float*)d_in[27];
    const float* bf1  = (const float*)d_in[28];
    const float* Wf2  = (const float*)d_in[29];
    const float* bf2  = (const float*)d_in[30];
    float* out = (float*)d_out;

    float *p_x1;
    bf16 *p_lnb, *p_h2b;
    cudaGetSymbolAddress((void**)&p_lnb, g_lnb);
    cudaGetSymbolAddress((void**)&p_x1,  g_x1);
    cudaGetSymbolAddress((void**)&p_h2b, g_h2b);

    // smem sizes (bytes)
    const int smemQKV  = 2 * (BM * 40 + 32 * 72)  * 2;   // 29696
    const int smem128  = 2 * (BM * 72 + 64 * 136) * 2;   // 71680
    const int smemRARV = (1536 + 1088 + 256 + 4608) * 4 + (64 * LDH + 128 * LDH) * 2; // ~57.6KB
    const int smemSC   = (1024 + 1088 + 64 + 512 + 4608) * 4 + 512 * 4 + (64 * LDH + 128 * LDH) * 2; // ~58.9KB

    static cudaStream_t s2 = nullptr;
    static cudaEvent_t evA = nullptr, evB = nullptr;
    if (s2 == nullptr) {
        cudaStreamCreateWithFlags(&s2, cudaStreamNonBlocking);
        cudaEventCreateWithFlags(&evA, cudaEventDisableTiming);
        cudaEventCreateWithFlags(&evB, cudaEventDisableTiming);
        cudaFuncSetAttribute(k_qkv2,  cudaFuncAttributeMaxDynamicSharedMemorySize, smemQKV);
        cudaFuncSetAttribute(k_wo,    cudaFuncAttributeMaxDynamicSharedMemorySize, smem128);
        cudaFuncSetAttribute(k_ffn1,  cudaFuncAttributeMaxDynamicSharedMemorySize, smem128);
        cudaFuncSetAttribute(k_ffn2,  cudaFuncAttributeMaxDynamicSharedMemorySize, smem128);
        cudaFuncSetAttribute(k_rarv,  cudaFuncAttributeMaxDynamicSharedMemorySize, smemRARV);
        cudaFuncSetAttribute(k_score, cudaFuncAttributeMaxDynamicSharedMemorySize, smemSC);
    }

    // 0. weights -> bf16, LN1 (main stream)
    k_cvtw<<<(340480 + 255) / 256, 256>>>(Wq, Wk, Wv, Wo, Wf1, Wf2, Wpa2, Wpv2, Ws1);
    k_ln<<<Mrows / 8, 256>>>(x, g1, b1, p_lnb);

    // fork: k_rarv on side stream, concurrent with QKV on main
    cudaEventRecord(evA, 0);
    cudaStreamWaitEvent(s2, evA, 0);
    k_rarv<<<dim3(NK / RT, 2), 256, smemRARV, s2>>>(rel, Wpa1, bpa1, bpa2, Wpv1, bpv1, bpv2);
    k_qkv2<<<dim3(Mrows / BM, 3), 256, smemQKV>>>(bq, bk, bv);
    cudaEventRecord(evB, s2);
    cudaStreamWaitEvent(0, evB, 0);

    // 3. scores + softmax + context (fused)
    k_score<<<dim3(NK / RT, Bc), 256, smemSC>>>(knn_idx, bs1, Ws2, bs2);

    // 4. x1 = x + ctx@Wo + bo ; h2 = LN2(x1)
    k_wo<<<dim3(Mrows / BM, Dc / 128), 256, smem128>>>(x, bo);
    k_ln<<<Mrows / 8, 256>>>(p_x1, g2, b2, p_h2b);

    // 5. FFN
    k_ffn1<<<dim3(Mrows / BM, Hc / 128), 256, smem128>>>(bf1);
    k_ffn2<<<dim3(Mrows / BM, Dc / 128), 256, smem128>>>(bf2, out);
}

// round 16
// speedup vs baseline: 1.0305x; 1.0305x over previous
#include <cuda_runtime.h>
#include <cstdint>
#include <cuda_bf16.h>
#include <mma.h>
#include <math.h>

using namespace nvcuda;

// Problem constants
#define Bc 2
#define Nc 32768
#define Kc 16
#define Dc 256
#define Ac 64
#define Vc 64
#define Hc 512
#define Mrows (Bc * Nc)   // 65536
#define NK (Nc * Kc)      // 524288

typedef __nv_bfloat16 bf16;

// -------- scratch (device globals) --------
__device__ bf16  g_lnb [(size_t)Mrows * Dc];
__device__ bf16  g_q   [(size_t)Mrows * Ac];
__device__ bf16  g_k   [(size_t)Mrows * Ac];
__device__ bf16  g_v   [(size_t)Mrows * Vc];
__device__ bf16  g_ctxb[(size_t)Mrows * Vc];
__device__ float g_x1  [(size_t)Mrows * Dc];
__device__ bf16  g_h2b [(size_t)Mrows * Dc];
__device__ bf16  g_hidb[(size_t)Mrows * Hc];
__device__ bf16  g_ra  [(size_t)NK * Ac];      // ra + bpa2 (bf16)
__device__ bf16  g_rv  [(size_t)NK * Vc];      // rv + bpv2 (bf16)

// bf16 weight copies
__device__ bf16 g_Wqb  [Dc * Ac];
__device__ bf16 g_Wkb  [Dc * Ac];
__device__ bf16 g_Wvb  [Dc * Vc];
__device__ bf16 g_Wob  [Vc * Dc];
__device__ bf16 g_Wf1b [Dc * Hc];
__device__ bf16 g_Wf2b [Hc * Dc];
__device__ bf16 g_Wpa2b[Ac * Ac];
__device__ bf16 g_Wpv2b[Vc * Vc];
__device__ bf16 g_Ws1b [Ac * Ac];

__device__ __forceinline__ float fast_tanh(float x) {
    float y;
    asm("tanh.approx.f32 %0, %1;" : "=f"(y) : "f"(x));
    return y;
}

__device__ __forceinline__ void cp16(void* dst, const void* src) {
    unsigned int s = (unsigned int)__cvta_generic_to_shared(dst);
    asm volatile("cp.async.cg.shared.global [%0], [%1], 16;" :: "r"(s), "l"(src));
}
__device__ __forceinline__ void cp_commit() {
    asm volatile("cp.async.commit_group;" ::: "memory");
}
__device__ __forceinline__ void cp_wait0() {
    asm volatile("cp.async.wait_group 0;" ::: "memory");
}

// ============================================================
// Weight fp32 -> bf16 conversion (incl. attention small weights)
// ============================================================
__global__ void k_cvtw(const float* __restrict__ Wq, const float* __restrict__ Wk,
                       const float* __restrict__ Wv, const float* __restrict__ Wo,
                       const float* __restrict__ Wf1, const float* __restrict__ Wf2,
                       const float* __restrict__ Wpa2, const float* __restrict__ Wpv2,
                       const float* __restrict__ Ws1) {
    int i = blockIdx.x * blockDim.x + threadIdx.x;
    const int S1 = Dc * Ac;
    const int S2 = S1 * 2;
    const int S3 = S1 * 3;
    const int S4 = S3 + Vc * Dc;
    const int S5 = S4 + Dc * Hc;
    const int S6 = S5 + Hc * Dc;
    const int S7 = S6 + Ac * Ac;
    const int S8 = S7 + Vc * Vc;
    const int S9 = S8 + Ac * Ac;
    if (i >= S9) return;
    if (i < S1)       g_Wqb  [i]      = __float2bfloat16(Wq  [i]);
    else if (i < S2)  g_Wkb  [i - S1] = __float2bfloat16(Wk  [i - S1]);
    else if (i < S3)  g_Wvb  [i - S2] = __float2bfloat16(Wv  [i - S2]);
    else if (i < S4)  g_Wob  [i - S3] = __float2bfloat16(Wo  [i - S3]);
    else if (i < S5)  g_Wf1b [i - S4] = __float2bfloat16(Wf1 [i - S4]);
    else if (i < S6)  g_Wf2b [i - S5] = __float2bfloat16(Wf2 [i - S5]);
    else if (i < S7)  g_Wpa2b[i - S6] = __float2bfloat16(Wpa2[i - S6]);
    else if (i < S8)  g_Wpv2b[i - S7] = __float2bfloat16(Wpv2[i - S7]);
    else              g_Ws1b [i - S8] = __float2bfloat16(Ws1 [i - S8]);
}

// ============================================================
// LayerNorm: out(bf16) = LN(in)*g + b.  one warp per row.
// ============================================================
__global__ void k_ln(const float* __restrict__ in,
                     const float* __restrict__ g, const float* __restrict__ b,
                     bf16* __restrict__ out) {
    const int row = blockIdx.x * 8 + (threadIdx.x >> 5);
    const int lane = threadIdx.x & 31;
    const float* p = in + (size_t)row * Dc;
    float v[8];
    #pragma unroll
    for (int i = 0; i < 8; i++) v[i] = p[lane + 32 * i];
    float s = 0.f;
    #pragma unroll
    for (int i = 0; i < 8; i++) s += v[i];
    #pragma unroll
    for (int o = 16; o; o >>= 1) s += __shfl_xor_sync(~0u, s, o);
    float m = s * (1.0f / Dc);
    float var = 0.f;
    #pragma unroll
    for (int i = 0; i < 8; i++) { float d = v[i] - m; var += d * d; }
    #pragma unroll
    for (int o = 16; o; o >>= 1) var += __shfl_xor_sync(~0u, var, o);
    float rstd = rsqrtf(var * (1.0f / Dc) + 1e-5f);
    bf16* q = out + (size_t)row * Dc;
    #pragma unroll
    for (int i = 0; i < 8; i++) {
        int d = lane + 32 * i;
        q[d] = __float2bfloat16((v[i] - m) * rstd * g[d] + b[d]);
    }
}

// ============================================================
// Pipelined bf16 wmma GEMM core.  BM=128, BK_/BN_ templated.
// ============================================================
#define BM 128

template<int BN_, int BK_, int ACT, bool HAS_RES, bool OUT_BF16>
__device__ __forceinline__ void gemm_core_bf16(
        const bf16* __restrict__ A, const bf16* __restrict__ B,
        const float* __restrict__ bias, const float* __restrict__ Res,
        void* __restrict__ Cv, int N, int K, int row0, int col0) {
    constexpr int LDA_ = BK_ + 8;
    constexpr int LDB_ = BN_ + 8;
    constexpr int ASZ  = BM * LDA_;
    constexpr int BSZ  = BK_ * LDB_;
    constexpr int NFRAG = BN_ / 32;
    constexpr int WCOLS = 16 * NFRAG;
    constexpr int LDE_  = WCOLS + 4;
    constexpr int AT = (BM * BK_ / 8) / 256;
    constexpr int BT = (BK_ * BN_ / 8 + 255) / 256;
    constexpr int KCH = BK_ / 8;

    extern __shared__ char smraw[];
    bf16* sb = (bf16*)smraw;
    bf16* Abuf[2] = { sb, sb + ASZ + BSZ };
    bf16* Bbuf[2] = { sb + ASZ, sb + 2 * ASZ + BSZ };

    const int tid = threadIdx.x;
    const int warp = tid >> 5, lane = tid & 31;
    const int wm = warp & 3;
    const int wn = warp >> 2;

    wmma::fragment<wmma::accumulator, 16, 16, 16, float> cf[2][NFRAG];
    #pragma unroll
    for (int i = 0; i < 2; i++)
        #pragma unroll
        for (int j = 0; j < NFRAG; j++) wmma::fill_fragment(cf[i][j], 0.f);

    {
        #pragma unroll
        for (int i = 0; i < AT; i++) {
            int idx = tid + i * 256;
            int r = idx / KCH, c8 = (idx % KCH) * 8;
            cp16(&Abuf[0][r * LDA_ + c8], A + (size_t)(row0 + r) * K + c8);
        }
        #pragma unroll
        for (int i = 0; i < BT; i++) {
            int idx = tid + i * 256;
            if (BT * 256 == BK_ * BN_ / 8 || idx < BK_ * BN_ / 8) {
                int r = idx / (BN_ / 8), c8 = (idx % (BN_ / 8)) * 8;
                cp16(&Bbuf[0][r * LDB_ + c8], B + (size_t)r * N + col0 + c8);
            }
        }
        cp_commit();
    }

    int buf = 0;
    for (int k0 = 0; k0 < K; k0 += BK_) {
        cp_wait0();
        __syncthreads();
        if (k0 + BK_ < K) {
            bf16* As = Abuf[buf ^ 1];
            bf16* Bs = Bbuf[buf ^ 1];
            #pragma unroll
            for (int i = 0; i < AT; i++) {
                int idx = tid + i * 256;
                int r = idx / KCH, c8 = (idx % KCH) * 8;
                cp16(&As[r * LDA_ + c8], A + (size_t)(row0 + r) * K + (k0 + BK_) + c8);
            }
            #pragma unroll
            for (int i = 0; i < BT; i++) {
                int idx = tid + i * 256;
                if (BT * 256 == BK_ * BN_ / 8 || idx < BK_ * BN_ / 8) {
                    int r = idx / (BN_ / 8), c8 = (idx % (BN_ / 8)) * 8;
                    cp16(&Bs[r * LDB_ + c8], B + (size_t)(k0 + BK_ + r) * N + col0 + c8);
                }
            }
            cp_commit();
        }
        const bf16* As = Abuf[buf];
        const bf16* Bs = Bbuf[buf];
        #pragma unroll
        for (int kk = 0; kk < BK_; kk += 16) {
            wmma::fragment<wmma::matrix_a, 16, 16, 16, bf16, wmma::row_major> af[2];
            wmma::fragment<wmma::matrix_b, 16, 16, 16, bf16, wmma::row_major> bf[NFRAG];
            #pragma unroll
            for (int i = 0; i < 2; i++)
                wmma::load_matrix_sync(af[i], &As[(wm * 32 + i * 16) * LDA_ + kk], LDA_);
            #pragma unroll
            for (int j = 0; j < NFRAG; j++)
                wmma::load_matrix_sync(bf[j], &Bs[kk * LDB_ + wn * WCOLS + j * 16], LDB_);
            #pragma unroll
            for (int i = 0; i < 2; i++)
                #pragma unroll
                for (int j = 0; j < NFRAG; j++)
                    wmma::mma_sync(cf[i][j], af[i], bf[j], cf[i][j]);
        }
        buf ^= 1;
    }

    __syncthreads();
    float* fs = (float*)smraw;
    float* Ep = fs + warp * (16 * LDE_);

    const int gr00 = row0 + wm * 32;
    const int gcb  = col0 + wn * WCOLS;
    float bvv[WCOLS / 32];
    #pragma unroll
    for (int cc = 0; cc < WCOLS / 32; cc++) bvv[cc] = bias[gcb + cc * 32 + lane];

    #pragma unroll
    for (int i = 0; i < 2; i++) {
        #pragma unroll
        for (int j = 0; j < NFRAG; j++)
            wmma::store_matrix_sync(&Ep[j * 16], cf[i][j], LDE_, wmma::mem_row_major);
        __syncwarp();
        const int gr0 = gr00 + i * 16;
        #pragma unroll
        for (int cc = 0; cc < WCOLS / 32; cc++) {
            const int cI = lane + cc * 32;
            #pragma unroll 4
            for (int r = 0; r < 16; r++) {
                float z = Ep[r * LDE_ + cI] + bvv[cc];
                if (ACT == 1) z = 0.5f * z * (1.f + erff(z * 0.70710678118654752f));
                if (HAS_RES) z += Res[(size_t)(gr0 + r) * N + gcb + cI];
                size_t off = (size_t)(gr0 + r) * N + gcb + cI;
                if (OUT_BF16) ((bf16*)Cv)[off] = __float2bfloat16(z);
                else          ((float*)Cv)[off] = z;
            }
        }
        __syncwarp();
    }
}

__global__ void __launch_bounds__(256, 2) k_qkv2(const float* __restrict__ bq,
                                                 const float* __restrict__ bk,
                                                 const float* __restrict__ bv) {
    const bf16* B; const float* bias; bf16* C;
    if (blockIdx.y == 0)      { B = g_Wqb; bias = bq; C = g_q; }
    else if (blockIdx.y == 1) { B = g_Wkb; bias = bk; C = g_k; }
    else                      { B = g_Wvb; bias = bv; C = g_v; }
    gemm_core_bf16<64, 32, 0, false, true>(g_lnb, B, bias, nullptr, C, 64, Dc, blockIdx.x * BM, 0);
}

__global__ void __launch_bounds__(256, 2) k_wo(const float* __restrict__ x,
                                               const float* __restrict__ bo) {
    gemm_core_bf16<128, 64, 0, true, false>(g_ctxb, g_Wob, bo, x, g_x1, Dc, Vc,
                                            blockIdx.x * BM, blockIdx.y * 128);
}

__global__ void __launch_bounds__(256, 2) k_ffn1(const float* __restrict__ bf1) {
    gemm_core_bf16<128, 64, 1, false, true>(g_h2b, g_Wf1b, bf1, nullptr, g_hidb, Hc, Dc,
                                            blockIdx.x * BM, blockIdx.y * 128);
}

__global__ void __launch_bounds__(256, 2) k_ffn2(const float* __restrict__ bf2,
                                                 float* __restrict__ C) {
    gemm_core_bf16<128, 64, 0, true, false>(g_hidb, g_Wf2b, bf2, g_x1, C, Dc, Hc,
                                            blockIdx.x * BM, blockIdx.y * 128);
}

// ============================================================
// k_rarv: one pass per blockIdx.y; 512-row tile; warp-private rows
// -> ZERO block barriers in the chunk loop.
// ============================================================
#define LDH 72   // bf16 stride
#define LDE2 68  // fp32 bias tile stride
#define LDE3 36  // fp32 half-pair staging stride
#define RT 512

__global__ void __launch_bounds__(256, 2) k_rarv(
        const float* __restrict__ rel,
        const float* __restrict__ Wpa1, const float* __restrict__ bpa1,
        const float* __restrict__ bpa2,
        const float* __restrict__ Wpv1, const float* __restrict__ bpv1,
        const float* __restrict__ bpv2) {
    extern __shared__ float sm[];
    float* rel_s = sm;                    // 1536
    float* biasT = rel_s + 1536;          // 1088
    float* w1s   = biasT + 1088;          // 256
    float* stg   = w1s + 256;             // 4608
    bf16*  W2s   = (bf16*)(stg + 4608);   // 64*72
    bf16*  Hb    = W2s + 64 * LDH;        // 128*72

    const int tid = threadIdx.x, lane = tid & 31, warp = tid >> 5;
    const int g0 = blockIdx.x * RT;
    const int pp = blockIdx.y;

    const float* W1g = pp ? Wpv1 : Wpa1;
    const float* B1g = pp ? bpv1 : bpa1;
    const float* B2g = pp ? bpv2 : bpa2;
    const bf16*  W2g = pp ? g_Wpv2b : g_Wpa2b;
    bf16* out = pp ? g_rv : g_ra;

    for (int i = tid; i < RT * 3; i += 256) rel_s[i] = rel[(size_t)g0 * 3 + i];
    for (int i = tid; i < 4096; i += 256) {
        int r = i >> 6, c = i & 63;
        W2s[r * LDH + c] = W2g[i];
    }
    for (int i = tid; i < 192; i += 256) w1s[i] = W1g[i];
    if (tid < 64) w1s[192 + tid] = B1g[tid];
    for (int i = tid; i < 16 * LDE2; i += 256) {
        int c = i % LDE2;
        biasT[i] = (c < 64) ? B2g[c] : 0.f;
    }
    __syncthreads();

    wmma::fragment<wmma::matrix_b, 16, 16, 16, bf16, wmma::row_major> bfr[4][4];
    #pragma unroll
    for (int k4 = 0; k4 < 4; k4++)
        #pragma unroll
        for (int j = 0; j < 4; j++)
            wmma::load_matrix_sync(bfr[k4][j], &W2s[(k4 * 16) * LDH + j * 16], LDH);

    const int j0 = 2 * lane, j1 = 2 * lane + 1;
    const float* W1 = w1s;
    for (int chunk = 0; chunk < 4; chunk++) {
        const int r0 = chunk * 128;
        // warp builds its OWN rows [warp*16, warp*16+16)
        #pragma unroll 4
        for (int pass = 0; pass < 16; pass++) {
            int r = warp * 16 + pass;
            float x0 = rel_s[(r0 + r) * 3];
            float x1 = rel_s[(r0 + r) * 3 + 1];
            float x2 = rel_s[(r0 + r) * 3 + 2];
            float h0 = fmaxf(fmaf(x2, W1[128 + j0], fmaf(x1, W1[64 + j0], fmaf(x0, W1[j0], W1[192 + j0]))), 0.f);
            float h1 = fmaxf(fmaf(x2, W1[128 + j1], fmaf(x1, W1[64 + j1], fmaf(x0, W1[j1], W1[192 + j1]))), 0.f);
            *(__nv_bfloat162*)&Hb[r * LDH + j0] = __floats2bfloat162_rn(h0, h1);
        }
        __syncwarp();

        wmma::fragment<wmma::accumulator, 16, 16, 16, float> acc[4];
        #pragma unroll
        for (int j = 0; j < 4; j++)
            wmma::load_matrix_sync(acc[j], &biasT[j * 16], LDE2, wmma::mem_row_major);
        #pragma unroll
        for (int k4 = 0; k4 < 4; k4++) {
            wmma::fragment<wmma::matrix_a, 16, 16, 16, bf16, wmma::row_major> af;
            wmma::load_matrix_sync(af, &Hb[(warp * 16) * LDH + k4 * 16], LDH);
            #pragma unroll
            for (int j = 0; j < 4; j++)
                wmma::mma_sync(acc[j], af, bfr[k4][j], acc[j]);
        }
        float* wstg = stg + warp * (16 * LDE3);
        const int row = lane & 15, half = lane >> 4;
        #pragma unroll
        for (int jp = 0; jp < 2; jp++) {
            wmma::store_matrix_sync(&wstg[0],  acc[jp * 2],     LDE3, wmma::mem_row_major);
            wmma::store_matrix_sync(&wstg[16], acc[jp * 2 + 1], LDE3, wmma::mem_row_major);
            __syncwarp();
            const float* rp = &wstg[row * LDE3 + half * 16];
            const size_t G = (size_t)(g0 + r0 + warp * 16 + row) * 64 + jp * 32 + half * 16;
            #pragma unroll
            for (int c = 0; c < 2; c++) {
                float4 a = *(const float4*)(rp + c * 8);
                float4 b = *(const float4*)(rp + c * 8 + 4);
                bf16 tmp[8];
                tmp[0] = __float2bfloat16(a.x); tmp[1] = __float2bfloat16(a.y);
                tmp[2] = __float2bfloat16(a.z); tmp[3] = __float2bfloat16(a.w);
                tmp[4] = __float2bfloat16(b.x); tmp[5] = __float2bfloat16(b.y);
                tmp[6] = __float2bfloat16(b.z); tmp[7] = __float2bfloat16(b.w);
                *(uint4*)&out[G + c * 8] = *(uint4*)tmp;
            }
            __syncwarp();
        }
    }
}

// ============================================================
// k_score: 512-row tile x batch; warp-private rows -> barrier-free
// chunk loop; one block barrier before fused softmax+ctx.
// ============================================================
__global__ void __launch_bounds__(256, 3) k_score(
        const int* __restrict__ knn_idx,
        const float* __restrict__ bs1,
        const float* __restrict__ Ws2, const float* __restrict__ bs2) {
    extern __shared__ float sm[];
    bf16*  q_sb  = (bf16*)sm;             // 2048 bf16 = 1024 floats
    float* biasT = sm + 1024;             // 1088
    float* wS2s  = biasT + 1088;          // 64
    float* sc_s  = wS2s + 64;             // 512
    float* stg   = sc_s + 512;            // 4608
    int*   idx_s = (int*)(stg + 4608);    // 512
    bf16*  Ws1b  = (bf16*)(idx_s + 512);  // 64*72
    bf16*  tb    = Ws1b + 64 * LDH;       // 128*72

    const int tid = threadIdx.x, lane = tid & 31, warp = tid >> 5;
    const int g0 = blockIdx.x * RT;
    const int b  = blockIdx.y;
    const int row = lane & 15, half = lane >> 4;

    for (int i = tid; i < 4096; i += 256) {
        int r = i >> 6, c = i & 63;
        Ws1b[r * LDH + c] = g_Ws1b[i];
    }
    for (int i = tid; i < 2048; i += 256) {
        int pt = i >> 6, a = i & 63;
        q_sb[i] = g_q[((size_t)b * Nc + (g0 >> 4) + pt) * 64 + a];
    }
    for (int i = tid; i < 512; i += 256) idx_s[i] = knn_idx[g0 + i];
    for (int i = tid; i < 16 * LDE2; i += 256) {
        int c = i % LDE2;
        biasT[i] = (c < 64) ? bs1[c] : 0.f;
    }
    if (tid < 64) wS2s[tid] = Ws2[tid];
    const float bS2v = bs2[0];
    __syncthreads();

    const int j0 = 2 * lane;
    for (int chunk = 0; chunk < 4; chunk++) {
        const int r0 = chunk * 128;
        // warp builds its OWN rows [warp*16, warp*16+16)
        #pragma unroll 4
        for (int pass = 0; pass < 16; pass++) {
            int r = warp * 16 + pass;
            int lr = r0 + r;
            int nb = idx_s[lr];
            __nv_bfloat162 qv = *(const __nv_bfloat162*)&q_sb[(lr >> 4) * 64 + j0];
            __nv_bfloat162 kv = *(const __nv_bfloat162*)&g_k[((size_t)b * Nc + nb) * 64 + j0];
            __nv_bfloat162 rab = *(const __nv_bfloat162*)&g_ra[(size_t)(g0 + lr) * 64 + j0];
            float t0 = fast_tanh(__bfloat162float(qv.x) - __bfloat162float(kv.x) + __bfloat162float(rab.x));
            float t1 = fast_tanh(__bfloat162float(qv.y) - __bfloat162float(kv.y) + __bfloat162float(rab.y));
            *(__nv_bfloat162*)&tb[r * LDH + j0] = __floats2bfloat162_rn(t0, t1);
        }
        __syncwarp();

        wmma::fragment<wmma::accumulator, 16, 16, 16, float> acc[4];
        #pragma unroll
        for (int j = 0; j < 4; j++)
            wmma::load_matrix_sync(acc[j], &biasT[j * 16], LDE2, wmma::mem_row_major);
        #pragma unroll
        for (int k4 = 0; k4 < 4; k4++) {
            wmma::fragment<wmma::matrix_a, 16, 16, 16, bf16, wmma::row_major> af;
            wmma::load_matrix_sync(af, &tb[(warp * 16) * LDH + k4 * 16], LDH);
            #pragma unroll
            for (int j = 0; j < 4; j++) {
                wmma::fragment<wmma::matrix_b, 16, 16, 16, bf16, wmma::row_major> bw;
                wmma::load_matrix_sync(bw, &Ws1b[(k4 * 16) * LDH + j * 16], LDH);
                wmma::mma_sync(acc[j], af, bw, acc[j]);
            }
        }
        float* wstg = stg + warp * (16 * LDE3);
        float p = 0.f;
        #pragma unroll
        for (int jp = 0; jp < 2; jp++) {
            wmma::store_matrix_sync(&wstg[0],  acc[jp * 2],     LDE3, wmma::mem_row_major);
            wmma::store_matrix_sync(&wstg[16], acc[jp * 2 + 1], LDE3, wmma::mem_row_major);
            __syncwarp();
            const float* rp = &wstg[row * LDE3 + half * 16];
            const int cb = jp * 32 + half * 16;
            #pragma unroll
            for (int c = 0; c < 4; c++) {
                float4 u = *(const float4*)(rp + c * 4);
                p = fmaf(fmaxf(u.x, 0.f), wS2s[cb + c * 4 + 0], p);
                p = fmaf(fmaxf(u.y, 0.f), wS2s[cb + c * 4 + 1], p);
                p = fmaf(fmaxf(u.z, 0.f), wS2s[cb + c * 4 + 2], p);
                p = fmaf(fmaxf(u.w, 0.f), wS2s[cb + c * 4 + 3], p);
            }
            __syncwarp();
        }
        p += __shfl_xor_sync(~0u, p, 16);
        if (half == 0)
            sc_s[r0 + warp * 16 + row] = p + bS2v;
    }
    __syncthreads();   // sc_s fully written before cross-warp softmax

    // ---- fused softmax + context: warp handles 4 points ----
    #pragma unroll
    for (int pi = 0; pi < 4; pi++) {
        const int pl = warp * 4 + pi;
        const int n  = (g0 >> 4) + pl;
        float s = -INFINITY;
        int nbl = 0;
        if (lane < 16) {
            s = sc_s[pl * 16 + lane] * 0.125f;
            nbl = idx_s[pl * 16 + lane];
        }
        float mx = s;
        #pragma unroll
        for (int o = 16; o; o >>= 1) mx = fmaxf(mx, __shfl_xor_sync(~0u, mx, o));
        float e = (lane < 16) ? __expf(s - mx) : 0.f;
        float se = e;
        #pragma unroll
        for (int o = 16; o; o >>= 1) se += __shfl_xor_sync(~0u, se, o);
        float wt = e / se;

        float acc0 = 0.f, acc1 = 0.f;
        #pragma unroll
        for (int kk = 0; kk < 16; kk++) {
            float ww = __shfl_sync(~0u, wt, kk);
            int nb  = __shfl_sync(~0u, nbl, kk);
            const bf16* vp = g_v + ((size_t)b * Nc + nb) * 64;
            const bf16* rvp = g_rv + (size_t)(g0 + pl * 16 + kk) * 64;
            acc0 += ww * (__bfloat162float(vp[lane])      + __bfloat162float(rvp[lane]));
            acc1 += ww * (__bfloat162float(vp[lane + 32]) + __bfloat162float(rvp[lane + 32]));
        }
        size_t obase = ((size_t)b * Nc + n) * 64;
        g_ctxb[obase + lane]      = __float2bfloat16(acc0);
        g_ctxb[obase + lane + 32] = __float2bfloat16(acc1);
    }
}

// ============================================================
extern "C" void kernel_launch(void* const* d_in, const int* in_sizes, int n_in,
                              void* d_out, int out_size) {
    const float* x       = (const float*)d_in[0];
    const int*   knn_idx = (const int*)  d_in[1];
    const float* rel     = (const float*)d_in[2];
    const float* g1 = (const float*)d_in[3];
    const float* b1 = (const float*)d_in[4];
    const float* g2 = (const float*)d_in[5];
    const float* b2 = (const float*)d_in[6];
    const float* Wq = (const float*)d_in[7];
    const float* bq = (const float*)d_in[8];
    const float* Wk = (const float*)d_in[9];
    const float* bk = (const float*)d_in[10];
    const float* Wv = (const float*)d_in[11];
    const float* bv = (const float*)d_in[12];
    const float* Wo = (const float*)d_in[13];
    const float* bo = (const float*)d_in[14];
    const float* Wpa1 = (const float*)d_in[15];
    const float* bpa1 = (const float*)d_in[16];
    const float* Wpa2 = (const float*)d_in[17];
    const float* bpa2 = (const float*)d_in[18];
    const float* Wpv1 = (const float*)d_in[19];
    const float* bpv1 = (const float*)d_in[20];
    const float* Wpv2 = (const float*)d_in[21];
    const float* bpv2 = (const float*)d_in[22];
    const float* Ws1  = (const float*)d_in[23];
    const float* bs1  = (const float*)d_in[24];
    const float* Ws2  = (const float*)d_in[25];
    const float* bs2  = (const float*)d_in[26];
    const float* Wf1  = (const float*)d_in[27];
    const float* bf1  = (const float*)d_in[28];
    const float* Wf2  = (const float*)d_in[29];
    const float* bf2  = (const float*)d_in[30];
    float* out = (float*)d_out;

    float *p_x1;
    bf16 *p_lnb, *p_h2b;
    cudaGetSymbolAddress((void**)&p_lnb, g_lnb);
    cudaGetSymbolAddress((void**)&p_x1,  g_x1);
    cudaGetSymbolAddress((void**)&p_h2b, g_h2b);

    // smem sizes (bytes)
    const int smemQKV  = 2 * (BM * 40 + 32 * 72)  * 2;   // 29696
    const int smem128  = 2 * (BM * 72 + 64 * 136) * 2;   // 71680
    const int smemRARV = (1536 + 1088 + 256 + 4608) * 4 + (64 * LDH + 128 * LDH) * 2; // ~57.6KB
    const int smemSC   = (1024 + 1088 + 64 + 512 + 4608) * 4 + 512 * 4 + (64 * LDH + 128 * LDH) * 2; // ~58.9KB

    static cudaStream_t s2 = nullptr;
    static cudaEvent_t evA = nullptr, evB = nullptr;
    if (s2 == nullptr) {
        cudaStreamCreateWithFlags(&s2, cudaStreamNonBlocking);
        cudaEventCreateWithFlags(&evA, cudaEventDisableTiming);
        cudaEventCreateWithFlags(&evB, cudaEventDisableTiming);
        cudaFuncSetAttribute(k_qkv2,  cudaFuncAttributeMaxDynamicSharedMemorySize, smemQKV);
        cudaFuncSetAttribute(k_wo,    cudaFuncAttributeMaxDynamicSharedMemorySize, smem128);
        cudaFuncSetAttribute(k_ffn1,  cudaFuncAttributeMaxDynamicSharedMemorySize, smem128);
        cudaFuncSetAttribute(k_ffn2,  cudaFuncAttributeMaxDynamicSharedMemorySize, smem128);
        cudaFuncSetAttribute(k_rarv,  cudaFuncAttributeMaxDynamicSharedMemorySize, smemRARV);
        cudaFuncSetAttribute(k_score, cudaFuncAttributeMaxDynamicSharedMemorySize, smemSC);
    }

    // 0. weights -> bf16, LN1 (main stream)
    k_cvtw<<<(340480 + 255) / 256, 256>>>(Wq, Wk, Wv, Wo, Wf1, Wf2, Wpa2, Wpv2, Ws1);
    k_ln<<<Mrows / 8, 256>>>(x, g1, b1, p_lnb);

    // fork: k_rarv on side stream, concurrent with QKV on main
    cudaEventRecord(evA, 0);
    cudaStreamWaitEvent(s2, evA, 0);
    k_rarv<<<dim3(NK / RT, 2), 256, smemRARV, s2>>>(rel, Wpa1, bpa1, bpa2, Wpv1, bpv1, bpv2);
    k_qkv2<<<dim3(Mrows / BM, 3), 256, smemQKV>>>(bq, bk, bv);
    cudaEventRecord(evB, s2);
    cudaStreamWaitEvent(0, evB, 0);

    // 3. scores + softmax + context (fused)
    k_score<<<dim3(NK / RT, Bc), 256, smemSC>>>(knn_idx, bs1, Ws2, bs2);

    // 4. x1 = x + ctx@Wo + bo ; h2 = LN2(x1)
    k_wo<<<dim3(Mrows / BM, Dc / 128), 256, smem128>>>(x, bo);
    k_ln<<<Mrows / 8, 256>>>(p_x1, g2, b2, p_h2b);

    // 5. FFN
    k_ffn1<<<dim3(Mrows / BM, Hc / 128), 256, smem128>>>(bf1);
    k_ffn2<<<dim3(Mrows / BM, Dc / 128), 256, smem128>>>(bf2, out);
}

// round 17
// speedup vs baseline: 1.0670x; 1.0355x over previous
#include <cuda_runtime.h>
#include <cstdint>
#include <cuda_bf16.h>
#include <mma.h>
#include <math.h>

using namespace nvcuda;

// Problem constants
#define Bc 2
#define Nc 32768
#define Kc 16
#define Dc 256
#define Ac 64
#define Vc 64
#define Hc 512
#define Mrows (Bc * Nc)   // 65536
#define NK (Nc * Kc)      // 524288

typedef __nv_bfloat16 bf16;

// -------- scratch (device globals) --------
__device__ bf16  g_lnb [(size_t)Mrows * Dc];
__device__ bf16  g_q   [(size_t)Mrows * Ac];
__device__ bf16  g_k   [(size_t)Mrows * Ac];
__device__ bf16  g_v   [(size_t)Mrows * Vc];
__device__ bf16  g_ctxb[(size_t)Mrows * Vc];
__device__ float g_x1  [(size_t)Mrows * Dc];
__device__ bf16  g_h2b [(size_t)Mrows * Dc];
__device__ bf16  g_hidb[(size_t)Mrows * Hc];
__device__ bf16  g_ra  [(size_t)NK * Ac];
__device__ bf16  g_rv  [(size_t)NK * Vc];

// bf16 weight copies
__device__ bf16 g_Wqb  [Dc * Ac];
__device__ bf16 g_Wkb  [Dc * Ac];
__device__ bf16 g_Wvb  [Dc * Vc];
__device__ bf16 g_Wob  [Vc * Dc];
__device__ bf16 g_Wf1b [Dc * Hc];
__device__ bf16 g_Wf2b [Hc * Dc];
__device__ bf16 g_Wpa2b[Ac * Ac];
__device__ bf16 g_Wpv2b[Vc * Vc];
__device__ bf16 g_Ws1b [Ac * Ac];

__device__ __forceinline__ float fast_tanh(float x) {
    float y;
    asm("tanh.approx.f32 %0, %1;" : "=f"(y) : "f"(x));
    return y;
}

__device__ __forceinline__ void cp16(void* dst, const void* src) {
    unsigned int s = (unsigned int)__cvta_generic_to_shared(dst);
    asm volatile("cp.async.cg.shared.global [%0], [%1], 16;" :: "r"(s), "l"(src));
}
__device__ __forceinline__ void cp_commit() {
    asm volatile("cp.async.commit_group;" ::: "memory");
}
__device__ __forceinline__ void cp_wait0() {
    asm volatile("cp.async.wait_group 0;" ::: "memory");
}

// ============================================================
// Weight fp32 -> bf16 conversion
// ============================================================
__global__ void k_cvtw(const float* __restrict__ Wq, const float* __restrict__ Wk,
                       const float* __restrict__ Wv, const float* __restrict__ Wo,
                       const float* __restrict__ Wf1, const float* __restrict__ Wf2,
                       const float* __restrict__ Wpa2, const float* __restrict__ Wpv2,
                       const float* __restrict__ Ws1) {
    int i = blockIdx.x * blockDim.x + threadIdx.x;
    const int S1 = Dc * Ac;
    const int S2 = S1 * 2;
    const int S3 = S1 * 3;
    const int S4 = S3 + Vc * Dc;
    const int S5 = S4 + Dc * Hc;
    const int S6 = S5 + Hc * Dc;
    const int S7 = S6 + Ac * Ac;
    const int S8 = S7 + Vc * Vc;
    const int S9 = S8 + Ac * Ac;
    if (i >= S9) return;
    if (i < S1)       g_Wqb  [i]      = __float2bfloat16(Wq  [i]);
    else if (i < S2)  g_Wkb  [i - S1] = __float2bfloat16(Wk  [i - S1]);
    else if (i < S3)  g_Wvb  [i - S2] = __float2bfloat16(Wv  [i - S2]);
    else if (i < S4)  g_Wob  [i - S3] = __float2bfloat16(Wo  [i - S3]);
    else if (i < S5)  g_Wf1b [i - S4] = __float2bfloat16(Wf1 [i - S4]);
    else if (i < S6)  g_Wf2b [i - S5] = __float2bfloat16(Wf2 [i - S5]);
    else if (i < S7)  g_Wpa2b[i - S6] = __float2bfloat16(Wpa2[i - S6]);
    else if (i < S8)  g_Wpv2b[i - S7] = __float2bfloat16(Wpv2[i - S7]);
    else              g_Ws1b [i - S8] = __float2bfloat16(Ws1 [i - S8]);
}

// ============================================================
// LayerNorm (LN1): out(bf16) = LN(in)*g + b.  one warp per row.
// ============================================================
__global__ void k_ln(const float* __restrict__ in,
                     const float* __restrict__ g, const float* __restrict__ b,
                     bf16* __restrict__ out) {
    const int row = blockIdx.x * 8 + (threadIdx.x >> 5);
    const int lane = threadIdx.x & 31;
    const float* p = in + (size_t)row * Dc;
    float v[8];
    #pragma unroll
    for (int i = 0; i < 8; i++) v[i] = p[lane + 32 * i];
    float s = 0.f;
    #pragma unroll
    for (int i = 0; i < 8; i++) s += v[i];
    #pragma unroll
    for (int o = 16; o; o >>= 1) s += __shfl_xor_sync(~0u, s, o);
    float m = s * (1.0f / Dc);
    float var = 0.f;
    #pragma unroll
    for (int i = 0; i < 8; i++) { float d = v[i] - m; var += d * d; }
    #pragma unroll
    for (int o = 16; o; o >>= 1) var += __shfl_xor_sync(~0u, var, o);
    float rstd = rsqrtf(var * (1.0f / Dc) + 1e-5f);
    bf16* q = out + (size_t)row * Dc;
    #pragma unroll
    for (int i = 0; i < 8; i++) {
        int d = lane + 32 * i;
        q[d] = __float2bfloat16((v[i] - m) * rstd * g[d] + b[d]);
    }
}

// ============================================================
// Pipelined bf16 wmma GEMM core.  BM=128, BK_/BN_ templated.
// ============================================================
#define BM 128

template<int BN_, int BK_, int ACT, bool HAS_RES, bool OUT_BF16>
__device__ __forceinline__ void gemm_core_bf16(
        const bf16* __restrict__ A, const bf16* __restrict__ B,
        const float* __restrict__ bias, const float* __restrict__ Res,
        void* __restrict__ Cv, int N, int K, int row0, int col0) {
    constexpr int LDA_ = BK_ + 8;
    constexpr int LDB_ = BN_ + 8;
    constexpr int ASZ  = BM * LDA_;
    constexpr int BSZ  = BK_ * LDB_;
    constexpr int NFRAG = BN_ / 32;
    constexpr int WCOLS = 16 * NFRAG;
    constexpr int LDE_  = WCOLS + 4;
    constexpr int AT = (BM * BK_ / 8) / 256;
    constexpr int BT = (BK_ * BN_ / 8 + 255) / 256;
    constexpr int KCH = BK_ / 8;

    extern __shared__ char smraw[];
    bf16* sb = (bf16*)smraw;
    bf16* Abuf[2] = { sb, sb + ASZ + BSZ };
    bf16* Bbuf[2] = { sb + ASZ, sb + 2 * ASZ + BSZ };

    const int tid = threadIdx.x;
    const int warp = tid >> 5, lane = tid & 31;
    const int wm = warp & 3;
    const int wn = warp >> 2;

    wmma::fragment<wmma::accumulator, 16, 16, 16, float> cf[2][NFRAG];
    #pragma unroll
    for (int i = 0; i < 2; i++)
        #pragma unroll
        for (int j = 0; j < NFRAG; j++) wmma::fill_fragment(cf[i][j], 0.f);

    {
        #pragma unroll
        for (int i = 0; i < AT; i++) {
            int idx = tid + i * 256;
            int r = idx / KCH, c8 = (idx % KCH) * 8;
            cp16(&Abuf[0][r * LDA_ + c8], A + (size_t)(row0 + r) * K + c8);
        }
        #pragma unroll
        for (int i = 0; i < BT; i++) {
            int idx = tid + i * 256;
            if (BT * 256 == BK_ * BN_ / 8 || idx < BK_ * BN_ / 8) {
                int r = idx / (BN_ / 8), c8 = (idx % (BN_ / 8)) * 8;
                cp16(&Bbuf[0][r * LDB_ + c8], B + (size_t)r * N + col0 + c8);
            }
        }
        cp_commit();
    }

    int buf = 0;
    for (int k0 = 0; k0 < K; k0 += BK_) {
        cp_wait0();
        __syncthreads();
        if (k0 + BK_ < K) {
            bf16* As = Abuf[buf ^ 1];
            bf16* Bs = Bbuf[buf ^ 1];
            #pragma unroll
            for (int i = 0; i < AT; i++) {
                int idx = tid + i * 256;
                int r = idx / KCH, c8 = (idx % KCH) * 8;
                cp16(&As[r * LDA_ + c8], A + (size_t)(row0 + r) * K + (k0 + BK_) + c8);
            }
            #pragma unroll
            for (int i = 0; i < BT; i++) {
                int idx = tid + i * 256;
                if (BT * 256 == BK_ * BN_ / 8 || idx < BK_ * BN_ / 8) {
                    int r = idx / (BN_ / 8), c8 = (idx % (BN_ / 8)) * 8;
                    cp16(&Bs[r * LDB_ + c8], B + (size_t)(k0 + BK_ + r) * N + col0 + c8);
                }
            }
            cp_commit();
        }
        const bf16* As = Abuf[buf];
        const bf16* Bs = Bbuf[buf];
        #pragma unroll
        for (int kk = 0; kk < BK_; kk += 16) {
            wmma::fragment<wmma::matrix_a, 16, 16, 16, bf16, wmma::row_major> af[2];
            wmma::fragment<wmma::matrix_b, 16, 16, 16, bf16, wmma::row_major> bf[NFRAG];
            #pragma unroll
            for (int i = 0; i < 2; i++)
                wmma::load_matrix_sync(af[i], &As[(wm * 32 + i * 16) * LDA_ + kk], LDA_);
            #pragma unroll
            for (int j = 0; j < NFRAG; j++)
                wmma::load_matrix_sync(bf[j], &Bs[kk * LDB_ + wn * WCOLS + j * 16], LDB_);
            #pragma unroll
            for (int i = 0; i < 2; i++)
                #pragma unroll
                for (int j = 0; j < NFRAG; j++)
                    wmma::mma_sync(cf[i][j], af[i], bf[j], cf[i][j]);
        }
        buf ^= 1;
    }

    __syncthreads();
    float* fs = (float*)smraw;
    float* Ep = fs + warp * (16 * LDE_);

    const int gr00 = row0 + wm * 32;
    const int gcb  = col0 + wn * WCOLS;
    float bvv[WCOLS / 32];
    #pragma unroll
    for (int cc = 0; cc < WCOLS / 32; cc++) bvv[cc] = bias[gcb + cc * 32 + lane];

    #pragma unroll
    for (int i = 0; i < 2; i++) {
        #pragma unroll
        for (int j = 0; j < NFRAG; j++)
            wmma::store_matrix_sync(&Ep[j * 16], cf[i][j], LDE_, wmma::mem_row_major);
        __syncwarp();
        const int gr0 = gr00 + i * 16;
        #pragma unroll
        for (int cc = 0; cc < WCOLS / 32; cc++) {
            const int cI = lane + cc * 32;
            #pragma unroll 4
            for (int r = 0; r < 16; r++) {
                float z = Ep[r * LDE_ + cI] + bvv[cc];
                if (ACT == 1) z = 0.5f * z * (1.f + erff(z * 0.70710678118654752f));
                if (HAS_RES) z += Res[(size_t)(gr0 + r) * N + gcb + cI];
                size_t off = (size_t)(gr0 + r) * N + gcb + cI;
                if (OUT_BF16) ((bf16*)Cv)[off] = __float2bfloat16(z);
                else          ((float*)Cv)[off] = z;
            }
        }
        __syncwarp();
    }
}

__global__ void __launch_bounds__(256, 2) k_qkv2(const float* __restrict__ bq,
                                                 const float* __restrict__ bk,
                                                 const float* __restrict__ bv) {
    const bf16* B; const float* bias; bf16* C;
    if (blockIdx.y == 0)      { B = g_Wqb; bias = bq; C = g_q; }
    else if (blockIdx.y == 1) { B = g_Wkb; bias = bk; C = g_k; }
    else                      { B = g_Wvb; bias = bv; C = g_v; }
    gemm_core_bf16<64, 32, 0, false, true>(g_lnb, B, bias, nullptr, C, 64, Dc, blockIdx.x * BM, 0);
}

__global__ void __launch_bounds__(256, 2) k_ffn1(const float* __restrict__ bf1) {
    gemm_core_bf16<128, 64, 1, false, true>(g_h2b, g_Wf1b, bf1, nullptr, g_hidb, Hc, Dc,
                                            blockIdx.x * BM, blockIdx.y * 128);
}

__global__ void __launch_bounds__(256, 2) k_ffn2(const float* __restrict__ bf2,
                                                 float* __restrict__ C) {
    gemm_core_bf16<128, 64, 0, true, false>(g_hidb, g_Wf2b, bf2, g_x1, C, Dc, Hc,
                                            blockIdx.x * BM, blockIdx.y * 128);
}

// ============================================================
// k_wo_ln: x1 = x + ctx@Wo + bo  (fp32 out) AND h2 = LN2(x1) (bf16)
// 64-row blocks, full 256 cols, K=64 single tile.
// ============================================================
#define WLDA 72
#define WLDB 264
#define WLDX 260

__global__ void __launch_bounds__(256, 2) k_wo_ln(
        const float* __restrict__ x, const float* __restrict__ bo,
        const float* __restrict__ g2, const float* __restrict__ b2) {
    extern __shared__ char smraw[];
    bf16* Ab = (bf16*)smraw;                       // 64*72
    bf16* Bb = Ab + 64 * WLDA;                     // 64*264
    float* x1s = (float*)smraw;                    // 64*260 fp32 (reused after GEMM)
    __shared__ float bo_s[256], g2_s[256], b2_s[256];

    const int tid = threadIdx.x, lane = tid & 31, warp = tid >> 5;
    const int row0 = blockIdx.x * 64;

    // loads
    #pragma unroll
    for (int i = 0; i < 2; i++) {
        int idx = tid + i * 256;      // 512 chunks of 8 for A (64 rows x 64 cols)
        int r = idx >> 3, c8 = (idx & 7) * 8;
        cp16(&Ab[r * WLDA + c8], g_ctxb + (size_t)(row0 + r) * Vc + c8);
    }
    #pragma unroll
    for (int i = 0; i < 8; i++) {
        int idx = tid + i * 256;      // 2048 chunks for B (64 x 256)
        int r = idx >> 5, c8 = (idx & 31) * 8;
        cp16(&Bb[r * WLDB + c8], g_Wob + (size_t)r * Dc + c8);
    }
    if (tid < 256) { bo_s[tid] = bo[tid]; g2_s[tid] = g2[tid]; b2_s[tid] = b2[tid]; }
    cp_commit();
    cp_wait0();
    __syncthreads();

    // GEMM: warp tile 32 rows x 64 cols. wm = warp&1, wn = warp>>1
    const int wm = warp & 1, wn = warp >> 1;
    wmma::fragment<wmma::accumulator, 16, 16, 16, float> acc[2][4];
    #pragma unroll
    for (int i = 0; i < 2; i++)
        #pragma unroll
        for (int j = 0; j < 4; j++) wmma::fill_fragment(acc[i][j], 0.f);
    #pragma unroll
    for (int kk = 0; kk < 64; kk += 16) {
        wmma::fragment<wmma::matrix_a, 16, 16, 16, bf16, wmma::row_major> af[2];
        wmma::fragment<wmma::matrix_b, 16, 16, 16, bf16, wmma::row_major> bw[4];
        #pragma unroll
        for (int i = 0; i < 2; i++)
            wmma::load_matrix_sync(af[i], &Ab[(wm * 32 + i * 16) * WLDA + kk], WLDA);
        #pragma unroll
        for (int j = 0; j < 4; j++)
            wmma::load_matrix_sync(bw[j], &Bb[kk * WLDB + wn * 64 + j * 16], WLDB);
        #pragma unroll
        for (int i = 0; i < 2; i++)
            #pragma unroll
            for (int j = 0; j < 4; j++)
                wmma::mma_sync(acc[i][j], af[i], bw[j], acc[i][j]);
    }
    __syncthreads();   // A/B reads done; smem becomes x1s

    #pragma unroll
    for (int i = 0; i < 2; i++)
        #pragma unroll
        for (int j = 0; j < 4; j++)
            wmma::store_matrix_sync(&x1s[(wm * 32 + i * 16) * WLDX + wn * 64 + j * 16],
                                    acc[i][j], WLDX, wmma::mem_row_major);
    __syncthreads();

    // bias + residual; write g_x1 and x1s
    #pragma unroll
    for (int i = 0; i < 64; i++) {
        int idx = tid + i * 256;
        int r = idx >> 8, c = idx & 255;
        float val = x1s[r * WLDX + c] + bo_s[c] + x[(size_t)(row0 + r) * Dc + c];
        x1s[r * WLDX + c] = val;
        g_x1[(size_t)(row0 + r) * Dc + c] = val;
    }
    __syncthreads();

    // LN2: warp handles 8 rows
    #pragma unroll
    for (int rr = 0; rr < 8; rr++) {
        int r = warp * 8 + rr;
        float v[8];
        #pragma unroll
        for (int i = 0; i < 8; i++) v[i] = x1s[r * WLDX + lane + 32 * i];
        float s = 0.f;
        #pragma unroll
        for (int i = 0; i < 8; i++) s += v[i];
        #pragma unroll
        for (int o = 16; o; o >>= 1) s += __shfl_xor_sync(~0u, s, o);
        float m = s * (1.0f / Dc);
        float var = 0.f;
        #pragma unroll
        for (int i = 0; i < 8; i++) { float d = v[i] - m; var += d * d; }
        #pragma unroll
        for (int o = 16; o; o >>= 1) var += __shfl_xor_sync(~0u, var, o);
        float rstd = rsqrtf(var * (1.0f / Dc) + 1e-5f);
        bf16* q = g_h2b + (size_t)(row0 + r) * Dc;
        #pragma unroll
        for (int i = 0; i < 8; i++) {
            int d = lane + 32 * i;
            q[d] = __float2bfloat16((v[i] - m) * rstd * g2_s[d] + b2_s[d]);
        }
    }
}

// ============================================================
// k_rarv: one pass per blockIdx.y; 512-row tile; warp-private rows.
// ============================================================
#define LDH 72
#define LDE2 68
#define LDE3 36
#define RT 512

__global__ void __launch_bounds__(256, 2) k_rarv(
        const float* __restrict__ rel,
        const float* __restrict__ Wpa1, const float* __restrict__ bpa1,
        const float* __restrict__ bpa2,
        const float* __restrict__ Wpv1, const float* __restrict__ bpv1,
        const float* __restrict__ bpv2) {
    extern __shared__ float sm[];
    float* rel_s = sm;                    // 1536
    float* biasT = rel_s + 1536;          // 1088
    float* w1s   = biasT + 1088;          // 256
    float* stg   = w1s + 256;             // 4608
    bf16*  W2s   = (bf16*)(stg + 4608);   // 64*72
    bf16*  Hb    = W2s + 64 * LDH;        // 128*72

    const int tid = threadIdx.x, lane = tid & 31, warp = tid >> 5;
    const int g0 = blockIdx.x * RT;
    const int pp = blockIdx.y;

    const float* W1g = pp ? Wpv1 : Wpa1;
    const float* B1g = pp ? bpv1 : bpa1;
    const float* B2g = pp ? bpv2 : bpa2;
    const bf16*  W2g = pp ? g_Wpv2b : g_Wpa2b;
    bf16* out = pp ? g_rv : g_ra;

    for (int i = tid; i < RT * 3; i += 256) rel_s[i] = rel[(size_t)g0 * 3 + i];
    for (int i = tid; i < 4096; i += 256) {
        int r = i >> 6, c = i & 63;
        W2s[r * LDH + c] = W2g[i];
    }
    for (int i = tid; i < 192; i += 256) w1s[i] = W1g[i];
    if (tid < 64) w1s[192 + tid] = B1g[tid];
    for (int i = tid; i < 16 * LDE2; i += 256) {
        int c = i % LDE2;
        biasT[i] = (c < 64) ? B2g[c] : 0.f;
    }
    __syncthreads();

    wmma::fragment<wmma::matrix_b, 16, 16, 16, bf16, wmma::row_major> bfr[4][4];
    #pragma unroll
    for (int k4 = 0; k4 < 4; k4++)
        #pragma unroll
        for (int j = 0; j < 4; j++)
            wmma::load_matrix_sync(bfr[k4][j], &W2s[(k4 * 16) * LDH + j * 16], LDH);

    const int j0 = 2 * lane, j1 = 2 * lane + 1;
    const float* W1 = w1s;
    for (int chunk = 0; chunk < 4; chunk++) {
        const int r0 = chunk * 128;
        #pragma unroll 4
        for (int pass = 0; pass < 16; pass++) {
            int r = warp * 16 + pass;
            float x0 = rel_s[(r0 + r) * 3];
            float x1 = rel_s[(r0 + r) * 3 + 1];
            float x2 = rel_s[(r0 + r) * 3 + 2];
            float h0 = fmaxf(fmaf(x2, W1[128 + j0], fmaf(x1, W1[64 + j0], fmaf(x0, W1[j0], W1[192 + j0]))), 0.f);
            float h1 = fmaxf(fmaf(x2, W1[128 + j1], fmaf(x1, W1[64 + j1], fmaf(x0, W1[j1], W1[192 + j1]))), 0.f);
            *(__nv_bfloat162*)&Hb[r * LDH + j0] = __floats2bfloat162_rn(h0, h1);
        }
        __syncwarp();

        wmma::fragment<wmma::accumulator, 16, 16, 16, float> acc[4];
        #pragma unroll
        for (int j = 0; j < 4; j++)
            wmma::load_matrix_sync(acc[j], &biasT[j * 16], LDE2, wmma::mem_row_major);
        #pragma unroll
        for (int k4 = 0; k4 < 4; k4++) {
            wmma::fragment<wmma::matrix_a, 16, 16, 16, bf16, wmma::row_major> af;
            wmma::load_matrix_sync(af, &Hb[(warp * 16) * LDH + k4 * 16], LDH);
            #pragma unroll
            for (int j = 0; j < 4; j++)
                wmma::mma_sync(acc[j], af, bfr[k4][j], acc[j]);
        }
        float* wstg = stg + warp * (16 * LDE3);
        const int row = lane & 15, half = lane >> 4;
        #pragma unroll
        for (int jp = 0; jp < 2; jp++) {
            wmma::store_matrix_sync(&wstg[0],  acc[jp * 2],     LDE3, wmma::mem_row_major);
            wmma::store_matrix_sync(&wstg[16], acc[jp * 2 + 1], LDE3, wmma::mem_row_major);
            __syncwarp();
            const float* rp = &wstg[row * LDE3 + half * 16];
            const size_t G = (size_t)(g0 + r0 + warp * 16 + row) * 64 + jp * 32 + half * 16;
            #pragma unroll
            for (int c = 0; c < 2; c++) {
                float4 a = *(const float4*)(rp + c * 8);
                float4 b = *(const float4*)(rp + c * 8 + 4);
                bf16 tmp[8];
                tmp[0] = __float2bfloat16(a.x); tmp[1] = __float2bfloat16(a.y);
                tmp[2] = __float2bfloat16(a.z); tmp[3] = __float2bfloat16(a.w);
                tmp[4] = __float2bfloat16(b.x); tmp[5] = __float2bfloat16(b.y);
                tmp[6] = __float2bfloat16(b.z); tmp[7] = __float2bfloat16(b.w);
                *(uint4*)&out[G + c * 8] = *(uint4*)tmp;
            }
            __syncwarp();
        }
    }
}

// ============================================================
// k_score: 512-row tile x batch; warp-private rows; fused softmax+ctx.
// ============================================================
__global__ void __launch_bounds__(256, 3) k_score(
        const int* __restrict__ knn_idx,
        const float* __restrict__ bs1,
        const float* __restrict__ Ws2, const float* __restrict__ bs2) {
    extern __shared__ float sm[];
    bf16*  q_sb  = (bf16*)sm;             // 2048 bf16 = 1024 floats
    float* biasT = sm + 1024;             // 1088
    float* wS2s  = biasT + 1088;          // 64
    float* sc_s  = wS2s + 64;             // 512
    float* stg   = sc_s + 512;            // 4608
    int*   idx_s = (int*)(stg + 4608);    // 512
    bf16*  Ws1b  = (bf16*)(idx_s + 512);  // 64*72
    bf16*  tb    = Ws1b + 64 * LDH;       // 128*72

    const int tid = threadIdx.x, lane = tid & 31, warp = tid >> 5;
    const int g0 = blockIdx.x * RT;
    const int b  = blockIdx.y;
    const int row = lane & 15, half = lane >> 4;

    for (int i = tid; i < 4096; i += 256) {
        int r = i >> 6, c = i & 63;
        Ws1b[r * LDH + c] = g_Ws1b[i];
    }
    for (int i = tid; i < 2048; i += 256) {
        int pt = i >> 6, a = i & 63;
        q_sb[i] = g_q[((size_t)b * Nc + (g0 >> 4) + pt) * 64 + a];
    }
    for (int i = tid; i < 512; i += 256) idx_s[i] = knn_idx[g0 + i];
    for (int i = tid; i < 16 * LDE2; i += 256) {
        int c = i % LDE2;
        biasT[i] = (c < 64) ? bs1[c] : 0.f;
    }
    if (tid < 64) wS2s[tid] = Ws2[tid];
    const float bS2v = bs2[0];
    __syncthreads();

    const int j0 = 2 * lane;
    for (int chunk = 0; chunk < 4; chunk++) {
        const int r0 = chunk * 128;
        #pragma unroll 4
        for (int pass = 0; pass < 16; pass++) {
            int r = warp * 16 + pass;
            int lr = r0 + r;
            int nb = idx_s[lr];
            __nv_bfloat162 qv = *(const __nv_bfloat162*)&q_sb[(lr >> 4) * 64 + j0];
            __nv_bfloat162 kv = *(const __nv_bfloat162*)&g_k[((size_t)b * Nc + nb) * 64 + j0];
            __nv_bfloat162 rab = *(const __nv_bfloat162*)&g_ra[(size_t)(g0 + lr) * 64 + j0];
            float t0 = fast_tanh(__bfloat162float(qv.x) - __bfloat162float(kv.x) + __bfloat162float(rab.x));
            float t1 = fast_tanh(__bfloat162float(qv.y) - __bfloat162float(kv.y) + __bfloat162float(rab.y));
            *(__nv_bfloat162*)&tb[r * LDH + j0] = __floats2bfloat162_rn(t0, t1);
        }
        __syncwarp();

        wmma::fragment<wmma::accumulator, 16, 16, 16, float> acc[4];
        #pragma unroll
        for (int j = 0; j < 4; j++)
            wmma::load_matrix_sync(acc[j], &biasT[j * 16], LDE2, wmma::mem_row_major);
        #pragma unroll
        for (int k4 = 0; k4 < 4; k4++) {
            wmma::fragment<wmma::matrix_a, 16, 16, 16, bf16, wmma::row_major> af;
            wmma::load_matrix_sync(af, &tb[(warp * 16) * LDH + k4 * 16], LDH);
            #pragma unroll
            for (int j = 0; j < 4; j++) {
                wmma::fragment<wmma::matrix_b, 16, 16, 16, bf16, wmma::row_major> bw;
                wmma::load_matrix_sync(bw, &Ws1b[(k4 * 16) * LDH + j * 16], LDH);
                wmma::mma_sync(acc[j], af, bw, acc[j]);
            }
        }
        float* wstg = stg + warp * (16 * LDE3);
        float p = 0.f;
        #pragma unroll
        for (int jp = 0; jp < 2; jp++) {
            wmma::store_matrix_sync(&wstg[0],  acc[jp * 2],     LDE3, wmma::mem_row_major);
            wmma::store_matrix_sync(&wstg[16], acc[jp * 2 + 1], LDE3, wmma::mem_row_major);
            __syncwarp();
            const float* rp = &wstg[row * LDE3 + half * 16];
            const int cb = jp * 32 + half * 16;
            #pragma unroll
            for (int c = 0; c < 4; c++) {
                float4 u = *(const float4*)(rp + c * 4);
                p = fmaf(fmaxf(u.x, 0.f), wS2s[cb + c * 4 + 0], p);
                p = fmaf(fmaxf(u.y, 0.f), wS2s[cb + c * 4 + 1], p);
                p = fmaf(fmaxf(u.z, 0.f), wS2s[cb + c * 4 + 2], p);
                p = fmaf(fmaxf(u.w, 0.f), wS2s[cb + c * 4 + 3], p);
            }
            __syncwarp();
        }
        p += __shfl_xor_sync(~0u, p, 16);
        if (half == 0)
            sc_s[r0 + warp * 16 + row] = p + bS2v;
    }
    __syncthreads();

    // ---- fused softmax + context ----
    #pragma unroll
    for (int pi = 0; pi < 4; pi++) {
        const int pl = warp * 4 + pi;
        const int n  = (g0 >> 4) + pl;
        float s = -INFINITY;
        int nbl = 0;
        if (lane < 16) {
            s = sc_s[pl * 16 + lane] * 0.125f;
            nbl = idx_s[pl * 16 + lane];
        }
        float mx = s;
        #pragma unroll
        for (int o = 16; o; o >>= 1) mx = fmaxf(mx, __shfl_xor_sync(~0u, mx, o));
        float e = (lane < 16) ? __expf(s - mx) : 0.f;
        float se = e;
        #pragma unroll
        for (int o = 16; o; o >>= 1) se += __shfl_xor_sync(~0u, se, o);
        float wt = e / se;

        float acc0 = 0.f, acc1 = 0.f;
        #pragma unroll
        for (int kk = 0; kk < 16; kk++) {
            float ww = __shfl_sync(~0u, wt, kk);
            int nb  = __shfl_sync(~0u, nbl, kk);
            const bf16* vp = g_v + ((size_t)b * Nc + nb) * 64;
            const bf16* rvp = g_rv + (size_t)(g0 + pl * 16 + kk) * 64;
            acc0 += ww * (__bfloat162float(vp[lane])      + __bfloat162float(rvp[lane]));
            acc1 += ww * (__bfloat162float(vp[lane + 32]) + __bfloat162float(rvp[lane + 32]));
        }
        size_t obase = ((size_t)b * Nc + n) * 64;
        g_ctxb[obase + lane]      = __float2bfloat16(acc0);
        g_ctxb[obase + lane + 32] = __float2bfloat16(acc1);
    }
}

// ============================================================
extern "C" void kernel_launch(void* const* d_in, const int* in_sizes, int n_in,
                              void* d_out, int out_size) {
    const float* x       = (const float*)d_in[0];
    const int*   knn_idx = (const int*)  d_in[1];
    const float* rel     = (const float*)d_in[2];
    const float* g1 = (const float*)d_in[3];
    const float* b1 = (const float*)d_in[4];
    const float* g2 = (const float*)d_in[5];
    const float* b2 = (const float*)d_in[6];
    const float* Wq = (const float*)d_in[7];
    const float* bq = (const float*)d_in[8];
    const float* Wk = (const float*)d_in[9];
    const float* bk = (const float*)d_in[10];
    const float* Wv = (const float*)d_in[11];
    const float* bv = (const float*)d_in[12];
    const float* Wo = (const float*)d_in[13];
    const float* bo = (const float*)d_in[14];
    const float* Wpa1 = (const float*)d_in[15];
    const float* bpa1 = (const float*)d_in[16];
    const float* Wpa2 = (const float*)d_in[17];
    const float* bpa2 = (const float*)d_in[18];
    const float* Wpv1 = (const float*)d_in[19];
    const float* bpv1 = (const float*)d_in[20];
    const float* Wpv2 = (const float*)d_in[21];
    const float* bpv2 = (const float*)d_in[22];
    const float* Ws1  = (const float*)d_in[23];
    const float* bs1  = (const float*)d_in[24];
    const float* Ws2  = (const float*)d_in[25];
    const float* bs2  = (const float*)d_in[26];
    const float* Wf1  = (const float*)d_in[27];
    const float* bf1  = (const float*)d_in[28];
    const float* Wf2  = (const float*)d_in[29];
    const float* bf2  = (const float*)d_in[30];
    float* out = (float*)d_out;

    bf16 *p_lnb;
    cudaGetSymbolAddress((void**)&p_lnb, g_lnb);

    // smem sizes (bytes)
    const int smemQKV  = 2 * (BM * 40 + 32 * 72)  * 2;   // 29696
    const int smem128  = 2 * (BM * 72 + 64 * 136) * 2;   // 71680
    const int smemRARV = (1536 + 1088 + 256 + 4608) * 4 + (64 * LDH + 128 * LDH) * 2;
    const int smemSC   = (1024 + 1088 + 64 + 512 + 4608) * 4 + 512 * 4 + (64 * LDH + 128 * LDH) * 2;
    const int smemWO   = 64 * WLDX * 4;                  // 66560 (>= GEMM phase 43008)

    static cudaStream_t s2 = nullptr;
    static cudaEvent_t evA = nullptr, evB = nullptr;
    if (s2 == nullptr) {
        cudaStreamCreateWithFlags(&s2, cudaStreamNonBlocking);
        cudaEventCreateWithFlags(&evA, cudaEventDisableTiming);
        cudaEventCreateWithFlags(&evB, cudaEventDisableTiming);
        cudaFuncSetAttribute(k_qkv2,  cudaFuncAttributeMaxDynamicSharedMemorySize, smemQKV);
        cudaFuncSetAttribute(k_wo_ln, cudaFuncAttributeMaxDynamicSharedMemorySize, smemWO);
        cudaFuncSetAttribute(k_ffn1,  cudaFuncAttributeMaxDynamicSharedMemorySize, smem128);
        cudaFuncSetAttribute(k_ffn2,  cudaFuncAttributeMaxDynamicSharedMemorySize, smem128);
        cudaFuncSetAttribute(k_rarv,  cudaFuncAttributeMaxDynamicSharedMemorySize, smemRARV);
        cudaFuncSetAttribute(k_score, cudaFuncAttributeMaxDynamicSharedMemorySize, smemSC);
    }

    // 0. weights -> bf16, LN1 (main stream)
    k_cvtw<<<(340480 + 255) / 256, 256>>>(Wq, Wk, Wv, Wo, Wf1, Wf2, Wpa2, Wpv2, Ws1);
    k_ln<<<Mrows / 8, 256>>>(x, g1, b1, p_lnb);

    // fork: k_rarv on side stream, concurrent with QKV on main
    cudaEventRecord(evA, 0);
    cudaStreamWaitEvent(s2, evA, 0);
    k_rarv<<<dim3(NK / RT, 2), 256, smemRARV, s2>>>(rel, Wpa1, bpa1, bpa2, Wpv1, bpv1, bpv2);
    k_qkv2<<<dim3(Mrows / BM, 3), 256, smemQKV>>>(bq, bk, bv);
    cudaEventRecord(evB, s2);
    cudaStreamWaitEvent(0, evB, 0);

    // 3. scores + softmax + context (fused)
    k_score<<<dim3(NK / RT, Bc), 256, smemSC>>>(knn_idx, bs1, Ws2, bs2);

    // 4. x1 = x + ctx@Wo + bo ; h2 = LN2(x1)   (fused)
    k_wo_ln<<<Mrows / 64, 256, smemWO>>>(x, bo, g2, b2);

    // 5. FFN
    k_ffn1<<<dim3(Mrows / BM, Hc / 128), 256, smem128>>>(bf1);
    k_ffn2<<<dim3(Mrows / BM, Dc / 128), 256, smem128>>>(bf2, out);
}